// round 1
// baseline (speedup 1.0000x reference)
#include <cuda_runtime.h>

// ---------------------------------------------------------------------------
// LePE attention, fp32 baseline.
// B=16, H=W=64, C=384, HEADS=12, hd=32, IDX=0 (vertical strips).
// x:      (16, 4096, 384)
// qkv_w:  (1152, 384)
// proj_w: (384, 384), proj_b: (384)
// lepe_w: (384, 1, 3, 3), lepe_b: (384)
// out:    (16, 4096, 384)
// ---------------------------------------------------------------------------

#define C_DIM   384
#define N_HEADS 12
#define HD      32
#define B_DIM   16
#define H_DIM   64
#define W_DIM   64
#define NTOK    4096      // H*W
#define L_DIM   64        // strip length (H)
#define M_TOTAL 65536     // B * NTOK rows
#define QKV_N   1152      // 3*C

// Scratch (device-global: no allocations allowed in kernel_launch)
__device__ float g_q[(size_t)M_TOTAL * C_DIM];     // (S, heads, L, hd)
__device__ float g_k[(size_t)M_TOTAL * C_DIM];
__device__ float g_v[(size_t)M_TOTAL * C_DIM];
__device__ float g_comb[(size_t)M_TOTAL * C_DIM];  // attn_out + lepe, (B, N, C)

// ---------------------------------------------------------------------------
// QKV GEMM: C[r, n] = sum_k Xsplit[r, k] * qkv_w[n, k]
//   r = (b*W + w)*64 + h  maps to x row  b*4096 + h*64 + w  (IDX=0 permutation)
//   epilogue scatters into g_q/g_k/g_v as (s, head, l, d)
// 128x128 tile, TK=8, 256 threads, 8x8 per thread.
// ---------------------------------------------------------------------------
__global__ __launch_bounds__(256) void qkv_gemm_kernel(
    const float* __restrict__ x, const float* __restrict__ wq)
{
    __shared__ float As[8][128];
    __shared__ float Bs[8][128];

    const int tid = threadIdx.x;
    const int m0 = blockIdx.x * 128;
    const int n0 = blockIdx.y * 128;

    const int lr = tid >> 1;          // 0..127
    const int lc = (tid & 1) * 4;     // 0 or 4

    // A tile row (m0+lr) -> permuted x row
    const int r   = m0 + lr;
    const int bb  = r >> 12;
    const int rem = r & 4095;
    const int w_  = rem >> 6;
    const int h_  = rem & 63;
    const float* aptr = x + (size_t)((bb << 12) + (h_ << 6) + w_) * C_DIM + lc;
    const float* bptr = wq + (size_t)(n0 + lr) * C_DIM + lc;

    const int tx = tid & 15;
    const int ty = tid >> 4;

    float acc[8][8];
#pragma unroll
    for (int i = 0; i < 8; i++)
#pragma unroll
        for (int j = 0; j < 8; j++) acc[i][j] = 0.f;

    for (int k0 = 0; k0 < C_DIM; k0 += 8) {
        float4 av = *(const float4*)(aptr + k0);
        float4 bv = *(const float4*)(bptr + k0);
        __syncthreads();
        As[lc + 0][lr] = av.x; As[lc + 1][lr] = av.y;
        As[lc + 2][lr] = av.z; As[lc + 3][lr] = av.w;
        Bs[lc + 0][lr] = bv.x; Bs[lc + 1][lr] = bv.y;
        Bs[lc + 2][lr] = bv.z; Bs[lc + 3][lr] = bv.w;
        __syncthreads();
#pragma unroll
        for (int k = 0; k < 8; k++) {
            float4 a0 = *(const float4*)&As[k][ty * 8];
            float4 a1 = *(const float4*)&As[k][ty * 8 + 4];
            float4 b0 = *(const float4*)&Bs[k][tx * 8];
            float4 b1 = *(const float4*)&Bs[k][tx * 8 + 4];
            float a[8] = {a0.x, a0.y, a0.z, a0.w, a1.x, a1.y, a1.z, a1.w};
            float b[8] = {b0.x, b0.y, b0.z, b0.w, b1.x, b1.y, b1.z, b1.w};
#pragma unroll
            for (int i = 0; i < 8; i++)
#pragma unroll
                for (int j = 0; j < 8; j++)
                    acc[i][j] += a[i] * b[j];
        }
    }

    // Scatter epilogue: n -> (which, head, d); m -> (s, l)
#pragma unroll
    for (int i = 0; i < 8; i++) {
        const int m = m0 + ty * 8 + i;
        const int s = m >> 6;
        const int l = m & 63;
#pragma unroll
        for (int j = 0; j < 8; j++) {
            const int n     = n0 + tx * 8 + j;
            const int which = n / C_DIM;       // constant per block (384 = 3*128)
            const int cc    = n - which * C_DIM;
            const int head  = cc >> 5;
            const int d     = cc & 31;
            float* dst = (which == 0) ? g_q : (which == 1) ? g_k : g_v;
            dst[(((size_t)s * N_HEADS + head) * L_DIM + l) * HD + d] = acc[i][j];
        }
    }
}

// ---------------------------------------------------------------------------
// Attention: one block per (s, head). L=64, hd=32. Writes attn output into
// g_comb at row index  b*4096 + w*64 + l  (torch's "no permute back").
// ---------------------------------------------------------------------------
__global__ __launch_bounds__(256) void attn_kernel()
{
    __shared__ float Qs[64][33];
    __shared__ float Ks[64][33];
    __shared__ float Vs[64][33];
    __shared__ float P[64][65];

    const int g   = blockIdx.x;            // s*12 + head
    const int tid = threadIdx.x;
    const size_t base = (size_t)g * 2048;  // 64*32 elements per (s, head)

    for (int i = tid; i < 2048; i += 256) {
        const int row = i >> 5, col = i & 31;
        Qs[row][col] = g_q[base + i];
        Ks[row][col] = g_k[base + i];
        Vs[row][col] = g_v[base + i];
    }
    __syncthreads();

    // scores (scaled)
    const float scale = 0.17677669529663687f;  // 1/sqrt(32)
    for (int idx = tid; idx < 4096; idx += 256) {
        const int l = idx >> 6, m = idx & 63;
        float s = 0.f;
#pragma unroll
        for (int d = 0; d < 32; d++) s += Qs[l][d] * Ks[m][d];
        P[l][m] = s * scale;
    }
    __syncthreads();

    // softmax: 8 warps x 8 rows each, lanes cover the 64 columns (2 per lane)
    const int warp = tid >> 5, lane = tid & 31;
#pragma unroll
    for (int rr = 0; rr < 8; rr++) {
        const int l = warp * 8 + rr;
        float v0 = P[l][lane], v1 = P[l][lane + 32];
        float mx = fmaxf(v0, v1);
#pragma unroll
        for (int o = 16; o; o >>= 1) mx = fmaxf(mx, __shfl_xor_sync(0xFFFFFFFFu, mx, o));
        const float e0 = __expf(v0 - mx);
        const float e1 = __expf(v1 - mx);
        float sm = e0 + e1;
#pragma unroll
        for (int o = 16; o; o >>= 1) sm += __shfl_xor_sync(0xFFFFFFFFu, sm, o);
        const float inv = 1.f / sm;
        P[l][lane]      = e0 * inv;
        P[l][lane + 32] = e1 * inv;
    }
    __syncthreads();

    // out = P @ V, scatter to g_comb
    const int s    = g / N_HEADS;
    const int head = g - s * N_HEADS;
    const int b    = s >> 6;
    const int w    = s & 63;
    float* dst = g_comb + (size_t)((b << 12) + (w << 6)) * C_DIM + head * HD;

    for (int idx = tid; idx < 2048; idx += 256) {
        const int l = idx >> 5, d = idx & 31;
        float acc = 0.f;
#pragma unroll
        for (int m = 0; m < 64; m++) acc += P[l][m] * Vs[m][d];
        dst[(size_t)l * C_DIM + d] = acc;
    }
}

// ---------------------------------------------------------------------------
// LePE: depthwise 3x3 over (H, W) layout, += into g_comb.
// One block per (b, h, w) token, 384 threads = channels.
// ---------------------------------------------------------------------------
__global__ __launch_bounds__(C_DIM) void lepe_kernel(
    const float* __restrict__ x, const float* __restrict__ lw,
    const float* __restrict__ lb)
{
    const int n  = blockIdx.x;     // b*4096 + hh*64 + ww
    const int c  = threadIdx.x;
    const int b  = n >> 12;
    const int sp = n & 4095;
    const int hh = sp >> 6;
    const int ww = sp & 63;

    float acc = lb[c];
    const float* wc = lw + c * 9;
    const size_t xbase = (size_t)(b << 12) * C_DIM;

#pragma unroll
    for (int dy = -1; dy <= 1; dy++) {
        const int y = hh + dy;
        if (y < 0 || y > 63) continue;
#pragma unroll
        for (int dx = -1; dx <= 1; dx++) {
            const int xx = ww + dx;
            if (xx < 0 || xx > 63) continue;
            acc += x[xbase + (size_t)((y << 6) + xx) * C_DIM + c] *
                   wc[(dy + 1) * 3 + (dx + 1)];
        }
    }
    g_comb[(size_t)n * C_DIM + c] += acc;
}

// ---------------------------------------------------------------------------
// Proj GEMM: out[m, n] = sum_k g_comb[m, k] * proj_w[n, k] + proj_b[n]
// ---------------------------------------------------------------------------
__global__ __launch_bounds__(256) void proj_gemm_kernel(
    const float* __restrict__ pw, const float* __restrict__ pb,
    float* __restrict__ out)
{
    __shared__ float As[8][128];
    __shared__ float Bs[8][128];

    const int tid = threadIdx.x;
    const int m0 = blockIdx.x * 128;
    const int n0 = blockIdx.y * 128;

    const int lr = tid >> 1;
    const int lc = (tid & 1) * 4;

    const float* aptr = g_comb + (size_t)(m0 + lr) * C_DIM + lc;
    const float* bptr = pw + (size_t)(n0 + lr) * C_DIM + lc;

    const int tx = tid & 15;
    const int ty = tid >> 4;

    float acc[8][8];
#pragma unroll
    for (int i = 0; i < 8; i++)
#pragma unroll
        for (int j = 0; j < 8; j++) acc[i][j] = 0.f;

    for (int k0 = 0; k0 < C_DIM; k0 += 8) {
        float4 av = *(const float4*)(aptr + k0);
        float4 bv = *(const float4*)(bptr + k0);
        __syncthreads();
        As[lc + 0][lr] = av.x; As[lc + 1][lr] = av.y;
        As[lc + 2][lr] = av.z; As[lc + 3][lr] = av.w;
        Bs[lc + 0][lr] = bv.x; Bs[lc + 1][lr] = bv.y;
        Bs[lc + 2][lr] = bv.z; Bs[lc + 3][lr] = bv.w;
        __syncthreads();
#pragma unroll
        for (int k = 0; k < 8; k++) {
            float4 a0 = *(const float4*)&As[k][ty * 8];
            float4 a1 = *(const float4*)&As[k][ty * 8 + 4];
            float4 b0 = *(const float4*)&Bs[k][tx * 8];
            float4 b1 = *(const float4*)&Bs[k][tx * 8 + 4];
            float a[8] = {a0.x, a0.y, a0.z, a0.w, a1.x, a1.y, a1.z, a1.w};
            float b[8] = {b0.x, b0.y, b0.z, b0.w, b1.x, b1.y, b1.z, b1.w};
#pragma unroll
            for (int i = 0; i < 8; i++)
#pragma unroll
                for (int j = 0; j < 8; j++)
                    acc[i][j] += a[i] * b[j];
        }
    }

#pragma unroll
    for (int i = 0; i < 8; i++) {
        const int m = m0 + ty * 8 + i;
#pragma unroll
        for (int j = 0; j < 8; j++) {
            const int n = n0 + tx * 8 + j;
            out[(size_t)m * C_DIM + n] = acc[i][j] + pb[n];
        }
    }
}

// ---------------------------------------------------------------------------
extern "C" void kernel_launch(void* const* d_in, const int* in_sizes, int n_in,
                              void* d_out, int out_size)
{
    const float* x      = (const float*)d_in[0];
    const float* qkv_w  = (const float*)d_in[1];
    const float* proj_w = (const float*)d_in[2];
    const float* proj_b = (const float*)d_in[3];
    const float* lepe_w = (const float*)d_in[4];
    const float* lepe_b = (const float*)d_in[5];
    float* out = (float*)d_out;
    (void)in_sizes; (void)n_in; (void)out_size;

    dim3 g_qkv(M_TOTAL / 128, QKV_N / 128);   // 512 x 9
    qkv_gemm_kernel<<<g_qkv, 256>>>(x, qkv_w);

    attn_kernel<<<B_DIM * W_DIM * N_HEADS, 256>>>();   // 12288 blocks

    lepe_kernel<<<B_DIM * NTOK, C_DIM>>>(x, lepe_w, lepe_b);

    dim3 g_proj(M_TOTAL / 128, C_DIM / 128);  // 512 x 3
    proj_gemm_kernel<<<g_proj, 256>>>(proj_w, proj_b, out);
}

// round 6
// speedup vs baseline: 1.6190x; 1.6190x over previous
#include <cuda_runtime.h>
#include <mma.h>
#include <cstdint>

using namespace nvcuda;

// ---------------------------------------------------------------------------
// LePE attention. GEMMs via WMMA tf32 as PURE row-major GEMMs (no fused
// permutation, no scatter). All layout logic lives in the attn kernel loads.
// B=16, H=W=64, C=384, HEADS=12, hd=32, IDX=0 (vertical strips).
// ---------------------------------------------------------------------------

#define C_DIM   384
#define N_HEADS 12
#define HD      32
#define B_DIM   16
#define NTOK    4096
#define L_DIM   64
#define M_TOTAL 65536
#define QKV_N   1152

// Scratch
__device__ float g_qkv[(size_t)M_TOTAL * QKV_N];   // (B*N, 3C) row-major
__device__ float g_comb[(size_t)M_TOTAL * C_DIM];  // attn_out + lepe, (B, N, C)

// ---------------------------------------------------------------------------
// Pure GEMM: D[m, n] = sum_k A[m, k] * Bw[n, k]  (+ bias[n] if bias != null)
// A: (M, 384) row-major. Bw: (N, 384) row-major. D: (M, ldD) row-major.
// 128x128 tile, BK=16, single smem buffer, register prefetch.
// 8 warps (2m x 4n), each warp 64x32 = 4x2 wmma m16n16k8 tf32 tiles.
// ---------------------------------------------------------------------------
#define BK  16
#define PAD 20   // floats per smem row (mult of 4)

__global__ __launch_bounds__(256)
void gemm_wmma_kernel(const float* __restrict__ A, const float* __restrict__ Bw,
                      const float* __restrict__ bias, float* __restrict__ D,
                      int ldD)
{
    __shared__ float As[128 * PAD];
    __shared__ float Bs[128 * PAD];

    const int tid  = threadIdx.x;
    const int lane = tid & 31;
    const int warp = tid >> 5;
    const int warpM = warp >> 2;       // 0..1  -> 64 rows
    const int warpN = warp & 3;        // 0..3  -> 32 cols
    const int m0 = blockIdx.x * 128;
    const int n0 = blockIdx.y * 128;

    // loader plan: 2 (row, c4) slots per thread per matrix
    const float* aSrc[2];
    const float* bSrc[2];
    int rowIdx[2], c4Idx[2];
#pragma unroll
    for (int i = 0; i < 2; i++) {
        const int f = tid + i * 256;       // 0..511
        rowIdx[i] = f >> 2;                // 0..127
        c4Idx[i]  = f & 3;
        aSrc[i] = A + (size_t)(m0 + rowIdx[i]) * C_DIM + c4Idx[i] * 4;
        bSrc[i] = Bw + (size_t)(n0 + rowIdx[i]) * C_DIM + c4Idx[i] * 4;
    }

    wmma::fragment<wmma::accumulator, 16, 16, 8, float> acc[4][2];
#pragma unroll
    for (int tr = 0; tr < 4; tr++)
#pragma unroll
        for (int tc = 0; tc < 2; tc++)
            wmma::fill_fragment(acc[tr][tc], 0.0f);

    const int NCHUNK = C_DIM / BK;  // 24
    const int aRow = warpM * 64;
    const int bRow = warpN * 32;

    float4 avA[2], avB[2];
#pragma unroll
    for (int i = 0; i < 2; i++) {
        avA[i] = *(const float4*)(aSrc[i]);
        avB[i] = *(const float4*)(bSrc[i]);
    }

    for (int c = 0; c < NCHUNK; c++) {
        __syncthreads();
#pragma unroll
        for (int i = 0; i < 2; i++) {
            *(float4*)&As[rowIdx[i] * PAD + c4Idx[i] * 4] = avA[i];
            *(float4*)&Bs[rowIdx[i] * PAD + c4Idx[i] * 4] = avB[i];
        }
        if (c + 1 < NCHUNK) {
            const int k0g = (c + 1) * BK;
#pragma unroll
            for (int i = 0; i < 2; i++) {
                avA[i] = *(const float4*)(aSrc[i] + k0g);
                avB[i] = *(const float4*)(bSrc[i] + k0g);
            }
        }
        __syncthreads();

#pragma unroll
        for (int ks = 0; ks < 2; ks++) {
            const int k0 = ks * 8;
            wmma::fragment<wmma::matrix_a, 16, 16, 8, wmma::precision::tf32,
                           wmma::row_major> af[4];
            wmma::fragment<wmma::matrix_b, 16, 16, 8, wmma::precision::tf32,
                           wmma::col_major> bf[2];
#pragma unroll
            for (int tr = 0; tr < 4; tr++) {
                wmma::load_matrix_sync(af[tr], As + (aRow + tr * 16) * PAD + k0, PAD);
#pragma unroll
                for (int e = 0; e < af[tr].num_elements; e++)
                    af[tr].x[e] = wmma::__float_to_tf32(af[tr].x[e]);
            }
#pragma unroll
            for (int tc = 0; tc < 2; tc++) {
                wmma::load_matrix_sync(bf[tc], Bs + (bRow + tc * 16) * PAD + k0, PAD);
#pragma unroll
                for (int e = 0; e < bf[tc].num_elements; e++)
                    bf[tc].x[e] = wmma::__float_to_tf32(bf[tc].x[e]);
            }
#pragma unroll
            for (int tr = 0; tr < 4; tr++)
#pragma unroll
                for (int tc = 0; tc < 2; tc++)
                    wmma::mma_sync(acc[tr][tc], af[tr], bf[tc], acc[tr][tc]);
        }
    }

    // epilogue: direct row-major store via store_matrix_sync, then bias fixup
#pragma unroll
    for (int tr = 0; tr < 4; tr++) {
#pragma unroll
        for (int tc = 0; tc < 2; tc++) {
            const int mBase = m0 + warpM * 64 + tr * 16;
            const int nBase = n0 + warpN * 32 + tc * 16;
            wmma::store_matrix_sync(D + (size_t)mBase * ldD + nBase,
                                    acc[tr][tc], ldD, wmma::mem_row_major);
        }
    }
    if (bias != nullptr) {
        __syncthreads();   // not strictly needed; cheap
        // add bias: each warp fixes its own 64x32 block
        const int mBase = m0 + warpM * 64;
        const int nBase = n0 + warpN * 32;
#pragma unroll
        for (int it = 0; it < 64; it++) {
            const int r = it;
            const int cc_ = lane;
            D[(size_t)(mBase + r) * ldD + nBase + cc_] += bias[nBase + cc_];
        }
    }
}

// ---------------------------------------------------------------------------
// Attention: one block per (s, head), s = b*64 + w. L=64, hd=32.
// Gathers Q/K/V straight from g_qkv rows (b*4096 + l*64 + w).
// Writes attn output to g_comb row (b*4096 + w*64 + l)  [faithful reshape].
// ---------------------------------------------------------------------------
__global__ __launch_bounds__(256) void attn_kernel()
{
    __shared__ float Qs[64][33];
    __shared__ float Ks[64][33];
    __shared__ float Vs[64][33];
    __shared__ float P[64][65];

    const int g    = blockIdx.x;           // s*12 + head
    const int tid  = threadIdx.x;
    const int s    = g / N_HEADS;
    const int head = g - s * N_HEADS;
    const int b    = s >> 6;
    const int w    = s & 63;

    // gather: for token l of the strip, row = b*4096 + l*64 + w
    const size_t rowBase = (size_t)(b << 12) + w;   // + l*64
    const int colQ = head * HD;                     // in [0, 384)
    for (int i = tid; i < 2048; i += 256) {
        const int l = i >> 5, d = i & 31;
        const size_t roff = (rowBase + (size_t)l * 64) * QKV_N + colQ + d;
        Qs[l][d] = g_qkv[roff];
        Ks[l][d] = g_qkv[roff + C_DIM];
        Vs[l][d] = g_qkv[roff + 2 * C_DIM];
    }
    __syncthreads();

    const float scale = 0.17677669529663687f;  // 1/sqrt(32)
    for (int idx = tid; idx < 4096; idx += 256) {
        const int l = idx >> 6, m = idx & 63;
        float sc = 0.f;
#pragma unroll
        for (int d = 0; d < 32; d++) sc += Qs[l][d] * Ks[m][d];
        P[l][m] = sc * scale;
    }
    __syncthreads();

    const int warp = tid >> 5, lane = tid & 31;
#pragma unroll
    for (int rr = 0; rr < 8; rr++) {
        const int l = warp * 8 + rr;
        float v0 = P[l][lane], v1 = P[l][lane + 32];
        float mx = fmaxf(v0, v1);
#pragma unroll
        for (int o = 16; o; o >>= 1) mx = fmaxf(mx, __shfl_xor_sync(0xFFFFFFFFu, mx, o));
        const float e0 = __expf(v0 - mx);
        const float e1 = __expf(v1 - mx);
        float sm = e0 + e1;
#pragma unroll
        for (int o = 16; o; o >>= 1) sm += __shfl_xor_sync(0xFFFFFFFFu, sm, o);
        const float inv = 1.f / sm;
        P[l][lane]      = e0 * inv;
        P[l][lane + 32] = e1 * inv;
    }
    __syncthreads();

    float* dst = g_comb + (size_t)((b << 12) + (w << 6)) * C_DIM + head * HD;
    for (int idx = tid; idx < 2048; idx += 256) {
        const int l = idx >> 5, d = idx & 31;
        float acc = 0.f;
#pragma unroll
        for (int m = 0; m < 64; m++) acc += P[l][m] * Vs[m][d];
        dst[(size_t)l * C_DIM + d] = acc;
    }
}

// ---------------------------------------------------------------------------
// LePE: depthwise 3x3, += into g_comb.
// ---------------------------------------------------------------------------
__global__ __launch_bounds__(C_DIM) void lepe_kernel(
    const float* __restrict__ x, const float* __restrict__ lw,
    const float* __restrict__ lb)
{
    const int n  = blockIdx.x;
    const int c  = threadIdx.x;
    const int b  = n >> 12;
    const int sp = n & 4095;
    const int hh = sp >> 6;
    const int ww = sp & 63;

    float acc = lb[c];
    const float* wc = lw + c * 9;
    const size_t xbase = (size_t)(b << 12) * C_DIM;

#pragma unroll
    for (int dy = -1; dy <= 1; dy++) {
        const int y = hh + dy;
        if (y < 0 || y > 63) continue;
#pragma unroll
        for (int dx = -1; dx <= 1; dx++) {
            const int xx = ww + dx;
            if (xx < 0 || xx > 63) continue;
            acc += x[xbase + (size_t)((y << 6) + xx) * C_DIM + c] *
                   wc[(dy + 1) * 3 + (dx + 1)];
        }
    }
    g_comb[(size_t)n * C_DIM + c] += acc;
}

// ---------------------------------------------------------------------------
extern "C" void kernel_launch(void* const* d_in, const int* in_sizes, int n_in,
                              void* d_out, int out_size)
{
    const float* x      = (const float*)d_in[0];
    const float* qkv_w  = (const float*)d_in[1];
    const float* proj_w = (const float*)d_in[2];
    const float* proj_b = (const float*)d_in[3];
    const float* lepe_w = (const float*)d_in[4];
    const float* lepe_b = (const float*)d_in[5];
    float* out = (float*)d_out;
    (void)in_sizes; (void)n_in; (void)out_size;

    float* qkv_out;
    cudaGetSymbolAddress((void**)&qkv_out, g_qkv);
    float* comb;
    cudaGetSymbolAddress((void**)&comb, g_comb);

    // qkv: (65536 x 384) @ (1152 x 384)^T -> (65536 x 1152), row-major, no bias
    dim3 g_qkv_grid(M_TOTAL / 128, QKV_N / 128);   // 512 x 9
    gemm_wmma_kernel<<<g_qkv_grid, 256>>>(x, qkv_w, nullptr, qkv_out, QKV_N);

    attn_kernel<<<B_DIM * 64 * N_HEADS, 256>>>();   // 12288 blocks

    lepe_kernel<<<B_DIM * NTOK, C_DIM>>>(x, lepe_w, lepe_b);

    // proj: (65536 x 384) @ (384 x 384)^T + b -> out
    dim3 g_proj_grid(M_TOTAL / 128, C_DIM / 128);  // 512 x 3
    gemm_wmma_kernel<<<g_proj_grid, 256>>>(comb, proj_w, proj_b, out, C_DIM);
}

// round 8
// speedup vs baseline: 1.6963x; 1.0477x over previous
#include <cuda_runtime.h>
#include <mma.h>
#include <cstdint>

using namespace nvcuda;

// ---------------------------------------------------------------------------
// LePE attention. GEMMs via WMMA tf32 pure row-major GEMMs.
// R8 (= R7 resubmit; prior run died to infra flake before kernel start):
//   tf32 pre-conversion in loader, double-buffered smem (1 barrier/chunk),
//   vectorized bias epilogue.
// B=16, H=W=64, C=384, HEADS=12, hd=32, IDX=0 (vertical strips).
// ---------------------------------------------------------------------------

#define C_DIM   384
#define N_HEADS 12
#define HD      32
#define B_DIM   16
#define NTOK    4096
#define L_DIM   64
#define M_TOTAL 65536
#define QKV_N   1152

// Scratch
__device__ float g_qkv[(size_t)M_TOTAL * QKV_N];   // (B*N, 3C) row-major
__device__ float g_comb[(size_t)M_TOTAL * C_DIM];  // attn_out + lepe, (B, N, C)

#define BK  16
#define PAD 20   // floats per smem row (mult of 4)

// ---------------------------------------------------------------------------
// Pure GEMM: D[m, n] = sum_k A[m, k] * Bw[n, k]  (+ bias[n] if bias != null)
// 128x128 tile, BK=16 double-buffered, register prefetch, tf32 pre-rounded
// in the loader. 8 warps (2m x 4n), warp = 4x2 wmma m16n16k8 tiles.
// ---------------------------------------------------------------------------
__global__ __launch_bounds__(256)
void gemm_wmma_kernel(const float* __restrict__ A, const float* __restrict__ Bw,
                      const float* __restrict__ bias, float* __restrict__ D,
                      int ldD)
{
    __shared__ float As[2][128 * PAD];
    __shared__ float Bs[2][128 * PAD];

    const int tid  = threadIdx.x;
    const int lane = tid & 31;
    const int warp = tid >> 5;
    const int warpM = warp >> 2;       // 0..1  -> 64 rows
    const int warpN = warp & 3;        // 0..3  -> 32 cols
    const int m0 = blockIdx.x * 128;
    const int n0 = blockIdx.y * 128;

    // loader plan: 2 (row, c4) slots per thread per matrix
    const float* aSrc[2];
    const float* bSrc[2];
    int rowIdx[2], c4Idx[2];
#pragma unroll
    for (int i = 0; i < 2; i++) {
        const int f = tid + i * 256;       // 0..511
        rowIdx[i] = f >> 2;                // 0..127
        c4Idx[i]  = f & 3;
        aSrc[i] = A + (size_t)(m0 + rowIdx[i]) * C_DIM + c4Idx[i] * 4;
        bSrc[i] = Bw + (size_t)(n0 + rowIdx[i]) * C_DIM + c4Idx[i] * 4;
    }

    wmma::fragment<wmma::accumulator, 16, 16, 8, float> acc[4][2];
#pragma unroll
    for (int tr = 0; tr < 4; tr++)
#pragma unroll
        for (int tc = 0; tc < 2; tc++)
            wmma::fill_fragment(acc[tr][tc], 0.0f);

    const int NCHUNK = C_DIM / BK;  // 24
    const int aRow = warpM * 64;
    const int bRow = warpN * 32;

    // prologue: chunk 0 -> regs (tf32-rounded) -> buf 0
    float4 avA[2], avB[2];
#pragma unroll
    for (int i = 0; i < 2; i++) {
        float4 a = *(const float4*)(aSrc[i]);
        float4 b = *(const float4*)(bSrc[i]);
        a.x = wmma::__float_to_tf32(a.x); a.y = wmma::__float_to_tf32(a.y);
        a.z = wmma::__float_to_tf32(a.z); a.w = wmma::__float_to_tf32(a.w);
        b.x = wmma::__float_to_tf32(b.x); b.y = wmma::__float_to_tf32(b.y);
        b.z = wmma::__float_to_tf32(b.z); b.w = wmma::__float_to_tf32(b.w);
        avA[i] = a; avB[i] = b;
        *(float4*)&As[0][rowIdx[i] * PAD + c4Idx[i] * 4] = a;
        *(float4*)&Bs[0][rowIdx[i] * PAD + c4Idx[i] * 4] = b;
    }
    __syncthreads();

    for (int c = 0; c < NCHUNK; c++) {
        const int buf = c & 1;
        // issue next chunk's global loads early (into registers)
        if (c + 1 < NCHUNK) {
            const int k0g = (c + 1) * BK;
#pragma unroll
            for (int i = 0; i < 2; i++) {
                avA[i] = *(const float4*)(aSrc[i] + k0g);
                avB[i] = *(const float4*)(bSrc[i] + k0g);
            }
        }

        const float* sa = As[buf];
        const float* sb = Bs[buf];
#pragma unroll
        for (int ks = 0; ks < 2; ks++) {
            const int k0 = ks * 8;
            wmma::fragment<wmma::matrix_a, 16, 16, 8, wmma::precision::tf32,
                           wmma::row_major> af[4];
            wmma::fragment<wmma::matrix_b, 16, 16, 8, wmma::precision::tf32,
                           wmma::col_major> bf[2];
#pragma unroll
            for (int tr = 0; tr < 4; tr++)
                wmma::load_matrix_sync(af[tr], sa + (aRow + tr * 16) * PAD + k0, PAD);
#pragma unroll
            for (int tc = 0; tc < 2; tc++)
                wmma::load_matrix_sync(bf[tc], sb + (bRow + tc * 16) * PAD + k0, PAD);
#pragma unroll
            for (int tr = 0; tr < 4; tr++)
#pragma unroll
                for (int tc = 0; tc < 2; tc++)
                    wmma::mma_sync(acc[tr][tc], af[tr], bf[tc], acc[tr][tc]);
        }

        // stage next chunk into the other buffer (round to tf32 first)
        if (c + 1 < NCHUNK) {
            const int nb = (c + 1) & 1;
#pragma unroll
            for (int i = 0; i < 2; i++) {
                float4 a = avA[i], b = avB[i];
                a.x = wmma::__float_to_tf32(a.x); a.y = wmma::__float_to_tf32(a.y);
                a.z = wmma::__float_to_tf32(a.z); a.w = wmma::__float_to_tf32(a.w);
                b.x = wmma::__float_to_tf32(b.x); b.y = wmma::__float_to_tf32(b.y);
                b.z = wmma::__float_to_tf32(b.z); b.w = wmma::__float_to_tf32(b.w);
                *(float4*)&As[nb][rowIdx[i] * PAD + c4Idx[i] * 4] = a;
                *(float4*)&Bs[nb][rowIdx[i] * PAD + c4Idx[i] * 4] = b;
            }
            __syncthreads();
        }
    }

    // ---- epilogue ----
    if (bias == nullptr) {
#pragma unroll
        for (int tr = 0; tr < 4; tr++)
#pragma unroll
            for (int tc = 0; tc < 2; tc++) {
                const int mBase = m0 + warpM * 64 + tr * 16;
                const int nBase = n0 + warpN * 32 + tc * 16;
                wmma::store_matrix_sync(D + (size_t)mBase * ldD + nBase,
                                        acc[tr][tc], ldD, wmma::mem_row_major);
            }
    } else {
        __syncthreads();   // smem free; reuse As[0] as staging
        float* stage = &As[0][0] + warp * 256;   // 16x16 per warp
#pragma unroll
        for (int tr = 0; tr < 4; tr++) {
#pragma unroll
            for (int tc = 0; tc < 2; tc++) {
                const int mBase = m0 + warpM * 64 + tr * 16;
                const int nBase = n0 + warpN * 32 + tc * 16;
                wmma::store_matrix_sync(stage, acc[tr][tc], 16, wmma::mem_row_major);
                __syncwarp();
#pragma unroll
                for (int t = 0; t < 2; t++) {
                    const int idx = lane + t * 32;   // float4 index 0..63
                    const int r  = idx >> 2;
                    const int c4 = idx & 3;
                    float4 v = ((const float4*)stage)[idx];
                    const float4 b4 = *(const float4*)&bias[nBase + c4 * 4];
                    v.x += b4.x; v.y += b4.y; v.z += b4.z; v.w += b4.w;
                    *(float4*)&D[(size_t)(mBase + r) * ldD + nBase + c4 * 4] = v;
                }
                __syncwarp();
            }
        }
    }
}

// ---------------------------------------------------------------------------
// Attention: one block per (s, head), s = b*64 + w. L=64, hd=32.
// ---------------------------------------------------------------------------
__global__ __launch_bounds__(256) void attn_kernel()
{
    __shared__ float Qs[64][33];
    __shared__ float Ks[64][33];
    __shared__ float Vs[64][33];
    __shared__ float P[64][65];

    const int g    = blockIdx.x;           // s*12 + head
    const int tid  = threadIdx.x;
    const int s    = g / N_HEADS;
    const int head = g - s * N_HEADS;
    const int b    = s >> 6;
    const int w    = s & 63;

    const size_t rowBase = (size_t)(b << 12) + w;   // + l*64
    const int colQ = head * HD;
    for (int i = tid; i < 2048; i += 256) {
        const int l = i >> 5, d = i & 31;
        const size_t roff = (rowBase + (size_t)l * 64) * QKV_N + colQ + d;
        Qs[l][d] = g_qkv[roff];
        Ks[l][d] = g_qkv[roff + C_DIM];
        Vs[l][d] = g_qkv[roff + 2 * C_DIM];
    }
    __syncthreads();

    const float scale = 0.17677669529663687f;  // 1/sqrt(32)
    for (int idx = tid; idx < 4096; idx += 256) {
        const int l = idx >> 6, m = idx & 63;
        float sc = 0.f;
#pragma unroll
        for (int d = 0; d < 32; d++) sc += Qs[l][d] * Ks[m][d];
        P[l][m] = sc * scale;
    }
    __syncthreads();

    const int warp = tid >> 5, lane = tid & 31;
#pragma unroll
    for (int rr = 0; rr < 8; rr++) {
        const int l = warp * 8 + rr;
        float v0 = P[l][lane], v1 = P[l][lane + 32];
        float mx = fmaxf(v0, v1);
#pragma unroll
        for (int o = 16; o; o >>= 1) mx = fmaxf(mx, __shfl_xor_sync(0xFFFFFFFFu, mx, o));
        const float e0 = __expf(v0 - mx);
        const float e1 = __expf(v1 - mx);
        float sm = e0 + e1;
#pragma unroll
        for (int o = 16; o; o >>= 1) sm += __shfl_xor_sync(0xFFFFFFFFu, sm, o);
        const float inv = 1.f / sm;
        P[l][lane]      = e0 * inv;
        P[l][lane + 32] = e1 * inv;
    }
    __syncthreads();

    float* dst = g_comb + (size_t)((b << 12) + (w << 6)) * C_DIM + head * HD;
    for (int idx = tid; idx < 2048; idx += 256) {
        const int l = idx >> 5, d = idx & 31;
        float acc = 0.f;
#pragma unroll
        for (int m = 0; m < 64; m++) acc += P[l][m] * Vs[m][d];
        dst[(size_t)l * C_DIM + d] = acc;
    }
}

// ---------------------------------------------------------------------------
// LePE: depthwise 3x3, += into g_comb.
// ---------------------------------------------------------------------------
__global__ __launch_bounds__(C_DIM) void lepe_kernel(
    const float* __restrict__ x, const float* __restrict__ lw,
    const float* __restrict__ lb)
{
    const int n  = blockIdx.x;
    const int c  = threadIdx.x;
    const int b  = n >> 12;
    const int sp = n & 4095;
    const int hh = sp >> 6;
    const int ww = sp & 63;

    float acc = lb[c];
    const float* wc = lw + c * 9;
    const size_t xbase = (size_t)(b << 12) * C_DIM;

#pragma unroll
    for (int dy = -1; dy <= 1; dy++) {
        const int y = hh + dy;
        if (y < 0 || y > 63) continue;
#pragma unroll
        for (int dx = -1; dx <= 1; dx++) {
            const int xx = ww + dx;
            if (xx < 0 || xx > 63) continue;
            acc += x[xbase + (size_t)((y << 6) + xx) * C_DIM + c] *
                   wc[(dy + 1) * 3 + (dx + 1)];
        }
    }
    g_comb[(size_t)n * C_DIM + c] += acc;
}

// ---------------------------------------------------------------------------
extern "C" void kernel_launch(void* const* d_in, const int* in_sizes, int n_in,
                              void* d_out, int out_size)
{
    const float* x      = (const float*)d_in[0];
    const float* qkv_w  = (const float*)d_in[1];
    const float* proj_w = (const float*)d_in[2];
    const float* proj_b = (const float*)d_in[3];
    const float* lepe_w = (const float*)d_in[4];
    const float* lepe_b = (const float*)d_in[5];
    float* out = (float*)d_out;
    (void)in_sizes; (void)n_in; (void)out_size;

    float* qkv_out;
    cudaGetSymbolAddress((void**)&qkv_out, g_qkv);
    float* comb;
    cudaGetSymbolAddress((void**)&comb, g_comb);

    // qkv: (65536 x 384) @ (1152 x 384)^T -> (65536 x 1152)
    dim3 g_qkv_grid(M_TOTAL / 128, QKV_N / 128);   // 512 x 9
    gemm_wmma_kernel<<<g_qkv_grid, 256>>>(x, qkv_w, nullptr, qkv_out, QKV_N);

    attn_kernel<<<B_DIM * 64 * N_HEADS, 256>>>();   // 12288 blocks

    lepe_kernel<<<B_DIM * NTOK, C_DIM>>>(x, lepe_w, lepe_b);

    // proj: (65536 x 384) @ (384 x 384)^T + b -> out
    dim3 g_proj_grid(M_TOTAL / 128, C_DIM / 128);  // 512 x 3
    gemm_wmma_kernel<<<g_proj_grid, 256>>>(comb, proj_w, proj_b, out, C_DIM);
}